// round 1
// baseline (speedup 1.0000x reference)
#include <cuda_runtime.h>

// Problem constants
#define B_    8192
#define NPAIR 32
#define BN    (B_ * NPAIR)     // 262144 items
#define KDIM  128              // 2*D  (concat input)
#define HDIM  128
#define ODIM  64
#define RREL  3
#define TPB   512
#define CHUNK 64
#define BUFCAP (TPB + CHUNK)   // 576

// Scratch: ui branch output + s-dtype flag
__device__ float g_ui[B_ * ODIM];
__device__ int   g_s_is64;

__device__ __forceinline__ float lrelu(float x) { return x >= 0.f ? x : 0.01f * x; }

// ---------------------------------------------------------------------------
// Kernel A: ui = lrelu(lrelu([u,i] @ W0 + b0) @ W1 + b1)   -> g_ui[B][64]
// 1024 blocks x 128 threads, 8 rows per block.
// Also: detect whether s is int64 (odd int32 words all zero) or int32.
// ---------------------------------------------------------------------------
__global__ __launch_bounds__(128) void ui_kernel(
    const float* __restrict__ u, const float* __restrict__ iv,
    const float* __restrict__ W0, const float* __restrict__ b0,
    const float* __restrict__ W1, const float* __restrict__ b1,
    const void* __restrict__ s_raw)
{
    __shared__ float sx[8][128];
    __shared__ float sh[8][128];
    int tid = threadIdx.x;
    int row0 = blockIdx.x * 8;

    if (blockIdx.x == 0 && tid == 0) {
        const int* p = (const int*)s_raw;
        int any = 0;
        #pragma unroll 16
        for (int q = 1; q < 257; q += 2) any |= p[q];
        g_s_is64 = (any == 0) ? 1 : 0;
    }

    #pragma unroll
    for (int rr = 0; rr < 8; rr++) {
        int row = row0 + rr;
        sx[rr][tid] = (tid < 64) ? u[row * 64 + tid] : iv[row * 64 + tid - 64];
    }
    __syncthreads();

    float acc[8];
    #pragma unroll
    for (int rr = 0; rr < 8; rr++) acc[rr] = 0.f;
    #pragma unroll 4
    for (int k = 0; k < 128; k++) {
        float w = W0[k * 128 + tid];
        #pragma unroll
        for (int rr = 0; rr < 8; rr++) acc[rr] += sx[rr][k] * w;
    }
    float bb = b0[tid];
    #pragma unroll
    for (int rr = 0; rr < 8; rr++) sh[rr][tid] = lrelu(acc[rr] + bb);
    __syncthreads();

    int j  = tid & 63;
    int rb = (tid >> 6) * 4;
    float a2[4] = {0.f, 0.f, 0.f, 0.f};
    #pragma unroll 4
    for (int k = 0; k < 128; k++) {
        float w = W1[k * 64 + j];
        #pragma unroll
        for (int q = 0; q < 4; q++) a2[q] += sh[rb + q][k] * w;
    }
    float b2 = b1[j];
    #pragma unroll
    for (int q = 0; q < 4; q++)
        g_ui[(row0 + rb + q) * 64 + j] = lrelu(a2[q] + b2);
}

// ---------------------------------------------------------------------------
// Kernel B: relation-compacted fused AO MLP + score.
// Dynamic smem layout (floats):
//   sW0 : [0, 16384)        128x128 layer-0 weights of current relation
//   sW1 : [16384, 24576)    128x64  layer-1 weights
//   sX  : [24576, 32768)    64x128 input chunk, aliased as H after GEMM1
//   sb0 : [32768, 32896)
//   sb1 : [32896, 32960)
//   sbuf: [32960, +576 ints) compaction buffer
// ---------------------------------------------------------------------------
#define SMEM_FLOATS (32960 + BUFCAP)
#define SMEM_BYTES  (SMEM_FLOATS * 4)

__device__ __forceinline__ void process_chunk(
    const int* __restrict__ list, int mm,
    const float* __restrict__ a_emb, const float* __restrict__ o_emb,
    const float* __restrict__ sW0, const float* __restrict__ sW1,
    const float* __restrict__ sb0, const float* __restrict__ sb1,
    float* __restrict__ sX, float* __restrict__ out, int tid)
{
    int lane = tid & 31;
    int warp = tid >> 5;          // 16 warps
    int m0 = warp * 4;            // 4 rows per warp / per thread-group

    // Load X chunk: row m = concat(a_emb[g], o_emb[g]); lane*4 covers k in [0,128)
    #pragma unroll
    for (int j = 0; j < 4; j++) {
        int m = m0 + j;
        float4 v = make_float4(0.f, 0.f, 0.f, 0.f);
        if (m < mm) {
            int g = list[m];
            const float* src = (lane < 16) ? (a_emb + (size_t)g * 64 + lane * 4)
                                           : (o_emb + (size_t)g * 64 + (lane - 16) * 4);
            v = *(const float4*)src;
        }
        *(float4*)&sX[m * 128 + lane * 4] = v;
    }
    __syncthreads();

    // GEMM1: H[64x128] = lrelu(X @ W0 + b0). Thread tile 4m x 4n.
    int n0 = lane * 4;
    float acc[4][4];
    #pragma unroll
    for (int i = 0; i < 4; i++)
        #pragma unroll
        for (int j = 0; j < 4; j++) acc[i][j] = 0.f;

    #pragma unroll 4
    for (int k = 0; k < 128; k++) {
        float x0 = sX[(m0 + 0) * 128 + k];
        float x1 = sX[(m0 + 1) * 128 + k];
        float x2 = sX[(m0 + 2) * 128 + k];
        float x3 = sX[(m0 + 3) * 128 + k];
        float4 w = *(const float4*)&sW0[k * 128 + n0];
        acc[0][0] += x0 * w.x; acc[0][1] += x0 * w.y; acc[0][2] += x0 * w.z; acc[0][3] += x0 * w.w;
        acc[1][0] += x1 * w.x; acc[1][1] += x1 * w.y; acc[1][2] += x1 * w.z; acc[1][3] += x1 * w.w;
        acc[2][0] += x2 * w.x; acc[2][1] += x2 * w.y; acc[2][2] += x2 * w.z; acc[2][3] += x2 * w.w;
        acc[3][0] += x3 * w.x; acc[3][1] += x3 * w.y; acc[3][2] += x3 * w.z; acc[3][3] += x3 * w.w;
    }
    __syncthreads();   // all X reads done before aliasing as H

    float4 bv = *(const float4*)&sb0[n0];
    #pragma unroll
    for (int i = 0; i < 4; i++) {
        float4 h;
        h.x = lrelu(acc[i][0] + bv.x);
        h.y = lrelu(acc[i][1] + bv.y);
        h.z = lrelu(acc[i][2] + bv.z);
        h.w = lrelu(acc[i][3] + bv.w);
        *(float4*)&sX[(m0 + i) * 128 + n0] = h;
    }
    __syncthreads();

    // GEMM2 + epilogue: o = lrelu(H @ W1 + b1); pred[g] = dot(ui[b], o).
    // Thread tile 4m x 2n (n = lane*2, warp covers all 64 n).
    int n2 = lane * 2;
    float a2[4][2];
    #pragma unroll
    for (int i = 0; i < 4; i++) { a2[i][0] = 0.f; a2[i][1] = 0.f; }

    #pragma unroll 4
    for (int k = 0; k < 128; k++) {
        float h0 = sX[(m0 + 0) * 128 + k];
        float h1 = sX[(m0 + 1) * 128 + k];
        float h2 = sX[(m0 + 2) * 128 + k];
        float h3 = sX[(m0 + 3) * 128 + k];
        float2 w = *(const float2*)&sW1[k * 64 + n2];
        a2[0][0] += h0 * w.x; a2[0][1] += h0 * w.y;
        a2[1][0] += h1 * w.x; a2[1][1] += h1 * w.y;
        a2[2][0] += h2 * w.x; a2[2][1] += h2 * w.y;
        a2[3][0] += h3 * w.x; a2[3][1] += h3 * w.y;
    }
    float bb0 = sb1[n2];
    float bb1 = sb1[n2 + 1];
    #pragma unroll
    for (int i = 0; i < 4; i++) {
        int m = m0 + i;
        float p = 0.f;
        int g = 0;
        if (m < mm) {
            g = list[m];
            int b = g >> 5;                       // N = 32
            float o0 = lrelu(a2[i][0] + bb0);
            float o1 = lrelu(a2[i][1] + bb1);
            p = o0 * g_ui[b * 64 + n2] + o1 * g_ui[b * 64 + n2 + 1];
        }
        #pragma unroll
        for (int off = 16; off; off >>= 1) p += __shfl_xor_sync(0xffffffffu, p, off);
        if (lane == 0 && m < mm) out[g] = p;
    }
    __syncthreads();   // protect sX/list reuse for next chunk
}

__global__ __launch_bounds__(TPB, 1) void ao_kernel(
    const float* __restrict__ a_emb, const float* __restrict__ o_emb,
    const void* __restrict__ s_raw,
    const float* __restrict__ aoW0, const float* __restrict__ aob0,
    const float* __restrict__ aoW1, const float* __restrict__ aob1,
    float* __restrict__ out, int nblocks)
{
    extern __shared__ float smem[];
    float* sW0  = smem;
    float* sW1  = smem + 16384;
    float* sX   = smem + 24576;
    float* sb0  = smem + 32768;
    float* sb1  = smem + 32896;
    int*   sbuf = (int*)(smem + 32960);
    __shared__ int scnt;

    int tid = threadIdx.x;
    const int* s32 = (const int*)s_raw;
    int is64 = g_s_is64;

    int per   = (BN + nblocks - 1) / nblocks;
    int start = blockIdx.x * per;
    int end   = min(BN, start + per);
    if (start >= end) return;

    for (int r = 0; r < RREL; r++) {
        // Load this relation's weights into smem (once per relation).
        const float4* w0s = (const float4*)(aoW0 + (size_t)r * KDIM * HDIM);
        for (int q = tid; q < 4096; q += TPB) ((float4*)sW0)[q] = w0s[q];
        const float4* w1s = (const float4*)(aoW1 + (size_t)r * HDIM * ODIM);
        for (int q = tid; q < 2048; q += TPB) ((float4*)sW1)[q] = w1s[q];
        if (tid < 128) sb0[tid] = aob0[r * 128 + tid];
        if (tid < 64)  sb1[tid] = aob1[r * 64 + tid];
        if (tid == 0)  scnt = 0;
        __syncthreads();

        // Scan item range; compact matches; fire dense 64-item chunks.
        for (int w0i = start; w0i < end; w0i += TPB) {
            int it = w0i + tid;
            if (it < end) {
                int sv = is64 ? s32[2 * it] : s32[it];
                if (sv == r) { int p = atomicAdd(&scnt, 1); sbuf[p] = it; }
            }
            __syncthreads();
            int cnt = scnt;
            int nfull = cnt >> 6;
            for (int c = 0; c < nfull; c++)
                process_chunk(sbuf + c * CHUNK, CHUNK, a_emb, o_emb,
                              sW0, sW1, sb0, sb1, sX, out, tid);
            int rem = cnt & (CHUNK - 1);
            int tv = 0;
            if (tid < rem) tv = sbuf[nfull * CHUNK + tid];
            __syncthreads();
            if (tid < rem) sbuf[tid] = tv;
            if (tid == 0) scnt = rem;
            __syncthreads();
        }
        int cnt = scnt;
        if (cnt > 0)
            process_chunk(sbuf, cnt, a_emb, o_emb, sW0, sW1, sb0, sb1, sX, out, tid);
        __syncthreads();
    }
}

// ---------------------------------------------------------------------------
// Launch
// ---------------------------------------------------------------------------
extern "C" void kernel_launch(void* const* d_in, const int* in_sizes, int n_in,
                              void* d_out, int out_size)
{
    const float* u    = (const float*)d_in[0];
    const float* iv   = (const float*)d_in[1];
    const float* a    = (const float*)d_in[2];
    const float* o    = (const float*)d_in[3];
    const void*  s    = d_in[4];
    const float* aoW0 = (const float*)d_in[5];
    const float* aob0 = (const float*)d_in[6];
    const float* aoW1 = (const float*)d_in[7];
    const float* aob1 = (const float*)d_in[8];
    const float* uiW0 = (const float*)d_in[9];
    const float* uib0 = (const float*)d_in[10];
    const float* uiW1 = (const float*)d_in[11];
    const float* uib1 = (const float*)d_in[12];
    float* out = (float*)d_out;

    cudaFuncSetAttribute(ao_kernel, cudaFuncAttributeMaxDynamicSharedMemorySize, SMEM_BYTES);
    int nsm = 148;
    cudaDeviceGetAttribute(&nsm, cudaDevAttrMultiProcessorCount, 0);

    ui_kernel<<<B_ / 8, 128>>>(u, iv, uiW0, uib0, uiW1, uib1, s);
    ao_kernel<<<nsm, TPB, SMEM_BYTES>>>(a, o, s, aoW0, aob0, aoW1, aob1, out, nsm);
}

// round 2
// speedup vs baseline: 1.0022x; 1.0022x over previous
#include <cuda_runtime.h>

// Problem constants
#define B_    8192
#define NPAIR 32
#define BN    (B_ * NPAIR)     // 262144 items
#define KDIM  128              // 2*D  (concat input)
#define HDIM  128
#define ODIM  64
#define RREL  3
#define TPB   512
#define CHUNK 64
#define BUFCAP (TPB + CHUNK)   // 576

// Scratch: ui branch output + s-dtype flag
__device__ float g_ui[B_ * ODIM];
__device__ int   g_s_is64;

__device__ __forceinline__ float lrelu(float x) { return x >= 0.f ? x : 0.01f * x; }

// ---------------------------------------------------------------------------
// Kernel A: ui = lrelu(lrelu([u,i] @ W0 + b0) @ W1 + b1)   -> g_ui[B][64]
// 1024 blocks x 128 threads, 8 rows per block.
// Also: detect whether s is int64 (odd int32 words all zero) or int32.
// ---------------------------------------------------------------------------
__global__ __launch_bounds__(128) void ui_kernel(
    const float* __restrict__ u, const float* __restrict__ iv,
    const float* __restrict__ W0, const float* __restrict__ b0,
    const float* __restrict__ W1, const float* __restrict__ b1,
    const void* __restrict__ s_raw)
{
    __shared__ float sx[8][128];
    __shared__ float sh[8][128];
    int tid = threadIdx.x;
    int row0 = blockIdx.x * 8;

    if (blockIdx.x == 0 && tid == 0) {
        const int* p = (const int*)s_raw;
        int any = 0;
        #pragma unroll 16
        for (int q = 1; q < 257; q += 2) any |= p[q];
        g_s_is64 = (any == 0) ? 1 : 0;
    }

    #pragma unroll
    for (int rr = 0; rr < 8; rr++) {
        int row = row0 + rr;
        sx[rr][tid] = (tid < 64) ? u[row * 64 + tid] : iv[row * 64 + tid - 64];
    }
    __syncthreads();

    float acc[8];
    #pragma unroll
    for (int rr = 0; rr < 8; rr++) acc[rr] = 0.f;
    #pragma unroll 4
    for (int k = 0; k < 128; k++) {
        float w = W0[k * 128 + tid];
        #pragma unroll
        for (int rr = 0; rr < 8; rr++) acc[rr] += sx[rr][k] * w;
    }
    float bb = b0[tid];
    #pragma unroll
    for (int rr = 0; rr < 8; rr++) sh[rr][tid] = lrelu(acc[rr] + bb);
    __syncthreads();

    int j  = tid & 63;
    int rb = (tid >> 6) * 4;
    float a2[4] = {0.f, 0.f, 0.f, 0.f};
    #pragma unroll 4
    for (int k = 0; k < 128; k++) {
        float w = W1[k * 64 + j];
        #pragma unroll
        for (int q = 0; q < 4; q++) a2[q] += sh[rb + q][k] * w;
    }
    float b2 = b1[j];
    #pragma unroll
    for (int q = 0; q < 4; q++)
        g_ui[(row0 + rb + q) * 64 + j] = lrelu(a2[q] + b2);
}

// ---------------------------------------------------------------------------
// Kernel B: relation-compacted fused AO MLP + score.
// Dynamic smem layout (floats):
//   sW0 : [0, 16384)        128x128 layer-0 weights of current relation
//   sW1 : [16384, 24576)    128x64  layer-1 weights
//   sX  : [24576, 32768)    64x128 input chunk, aliased as H after GEMM1
//   sb0 : [32768, 32896)
//   sb1 : [32896, 32960)
//   sbuf: [32960, +576 ints) compaction buffer
// ---------------------------------------------------------------------------
#define SMEM_FLOATS (32960 + BUFCAP)
#define SMEM_BYTES  (SMEM_FLOATS * 4)

__device__ __forceinline__ void process_chunk(
    const int* __restrict__ list, int mm,
    const float* __restrict__ a_emb, const float* __restrict__ o_emb,
    const float* __restrict__ sW0, const float* __restrict__ sW1,
    const float* __restrict__ sb0, const float* __restrict__ sb1,
    float* __restrict__ sX, float* __restrict__ out, int tid)
{
    int lane = tid & 31;
    int warp = tid >> 5;          // 16 warps
    int m0 = warp * 4;            // 4 rows per warp / per thread-group

    // Load X chunk: row m = concat(a_emb[g], o_emb[g]); lane*4 covers k in [0,128)
    #pragma unroll
    for (int j = 0; j < 4; j++) {
        int m = m0 + j;
        float4 v = make_float4(0.f, 0.f, 0.f, 0.f);
        if (m < mm) {
            int g = list[m];
            const float* src = (lane < 16) ? (a_emb + (size_t)g * 64 + lane * 4)
                                           : (o_emb + (size_t)g * 64 + (lane - 16) * 4);
            v = *(const float4*)src;
        }
        *(float4*)&sX[m * 128 + lane * 4] = v;
    }
    __syncthreads();

    // GEMM1: H[64x128] = lrelu(X @ W0 + b0). Thread tile 4m x 4n.
    int n0 = lane * 4;
    float acc[4][4];
    #pragma unroll
    for (int i = 0; i < 4; i++)
        #pragma unroll
        for (int j = 0; j < 4; j++) acc[i][j] = 0.f;

    #pragma unroll 4
    for (int k = 0; k < 128; k++) {
        float x0 = sX[(m0 + 0) * 128 + k];
        float x1 = sX[(m0 + 1) * 128 + k];
        float x2 = sX[(m0 + 2) * 128 + k];
        float x3 = sX[(m0 + 3) * 128 + k];
        float4 w = *(const float4*)&sW0[k * 128 + n0];
        acc[0][0] += x0 * w.x; acc[0][1] += x0 * w.y; acc[0][2] += x0 * w.z; acc[0][3] += x0 * w.w;
        acc[1][0] += x1 * w.x; acc[1][1] += x1 * w.y; acc[1][2] += x1 * w.z; acc[1][3] += x1 * w.w;
        acc[2][0] += x2 * w.x; acc[2][1] += x2 * w.y; acc[2][2] += x2 * w.z; acc[2][3] += x2 * w.w;
        acc[3][0] += x3 * w.x; acc[3][1] += x3 * w.y; acc[3][2] += x3 * w.z; acc[3][3] += x3 * w.w;
    }
    __syncthreads();   // all X reads done before aliasing as H

    float4 bv = *(const float4*)&sb0[n0];
    #pragma unroll
    for (int i = 0; i < 4; i++) {
        float4 h;
        h.x = lrelu(acc[i][0] + bv.x);
        h.y = lrelu(acc[i][1] + bv.y);
        h.z = lrelu(acc[i][2] + bv.z);
        h.w = lrelu(acc[i][3] + bv.w);
        *(float4*)&sX[(m0 + i) * 128 + n0] = h;
    }
    __syncthreads();

    // GEMM2 + epilogue: o = lrelu(H @ W1 + b1); pred[g] = dot(ui[b], o).
    // Thread tile 4m x 2n (n = lane*2, warp covers all 64 n).
    int n2 = lane * 2;
    float a2[4][2];
    #pragma unroll
    for (int i = 0; i < 4; i++) { a2[i][0] = 0.f; a2[i][1] = 0.f; }

    #pragma unroll 4
    for (int k = 0; k < 128; k++) {
        float h0 = sX[(m0 + 0) * 128 + k];
        float h1 = sX[(m0 + 1) * 128 + k];
        float h2 = sX[(m0 + 2) * 128 + k];
        float h3 = sX[(m0 + 3) * 128 + k];
        float2 w = *(const float2*)&sW1[k * 64 + n2];
        a2[0][0] += h0 * w.x; a2[0][1] += h0 * w.y;
        a2[1][0] += h1 * w.x; a2[1][1] += h1 * w.y;
        a2[2][0] += h2 * w.x; a2[2][1] += h2 * w.y;
        a2[3][0] += h3 * w.x; a2[3][1] += h3 * w.y;
    }
    float bb0 = sb1[n2];
    float bb1 = sb1[n2 + 1];
    #pragma unroll
    for (int i = 0; i < 4; i++) {
        int m = m0 + i;
        float p = 0.f;
        int g = 0;
        if (m < mm) {
            g = list[m];
            int b = g >> 5;                       // N = 32
            float o0 = lrelu(a2[i][0] + bb0);
            float o1 = lrelu(a2[i][1] + bb1);
            p = o0 * g_ui[b * 64 + n2] + o1 * g_ui[b * 64 + n2 + 1];
        }
        #pragma unroll
        for (int off = 16; off; off >>= 1) p += __shfl_xor_sync(0xffffffffu, p, off);
        if (lane == 0 && m < mm) out[g] = p;
    }
    __syncthreads();   // protect sX/list reuse for next chunk
}

__global__ __launch_bounds__(TPB, 1) void ao_kernel(
    const float* __restrict__ a_emb, const float* __restrict__ o_emb,
    const void* __restrict__ s_raw,
    const float* __restrict__ aoW0, const float* __restrict__ aob0,
    const float* __restrict__ aoW1, const float* __restrict__ aob1,
    float* __restrict__ out, int nblocks)
{
    extern __shared__ float smem[];
    float* sW0  = smem;
    float* sW1  = smem + 16384;
    float* sX   = smem + 24576;
    float* sb0  = smem + 32768;
    float* sb1  = smem + 32896;
    int*   sbuf = (int*)(smem + 32960);
    __shared__ int scnt;

    int tid = threadIdx.x;
    const int* s32 = (const int*)s_raw;
    int is64 = g_s_is64;

    int per   = (BN + nblocks - 1) / nblocks;
    int start = blockIdx.x * per;
    int end   = min(BN, start + per);
    if (start >= end) return;

    for (int r = 0; r < RREL; r++) {
        // Load this relation's weights into smem (once per relation).
        const float4* w0s = (const float4*)(aoW0 + (size_t)r * KDIM * HDIM);
        for (int q = tid; q < 4096; q += TPB) ((float4*)sW0)[q] = w0s[q];
        const float4* w1s = (const float4*)(aoW1 + (size_t)r * HDIM * ODIM);
        for (int q = tid; q < 2048; q += TPB) ((float4*)sW1)[q] = w1s[q];
        if (tid < 128) sb0[tid] = aob0[r * 128 + tid];
        if (tid < 64)  sb1[tid] = aob1[r * 64 + tid];
        if (tid == 0)  scnt = 0;
        __syncthreads();

        // Scan item range; compact matches; fire dense 64-item chunks.
        for (int w0i = start; w0i < end; w0i += TPB) {
            int it = w0i + tid;
            if (it < end) {
                int sv = is64 ? s32[2 * it] : s32[it];
                if (sv == r) { int p = atomicAdd(&scnt, 1); sbuf[p] = it; }
            }
            __syncthreads();
            int cnt = scnt;
            int nfull = cnt >> 6;
            for (int c = 0; c < nfull; c++)
                process_chunk(sbuf + c * CHUNK, CHUNK, a_emb, o_emb,
                              sW0, sW1, sb0, sb1, sX, out, tid);
            int rem = cnt & (CHUNK - 1);
            int tv = 0;
            if (tid < rem) tv = sbuf[nfull * CHUNK + tid];
            __syncthreads();
            if (tid < rem) sbuf[tid] = tv;
            if (tid == 0) scnt = rem;
            __syncthreads();
        }
        int cnt = scnt;
        if (cnt > 0)
            process_chunk(sbuf, cnt, a_emb, o_emb, sW0, sW1, sb0, sb1, sX, out, tid);
        __syncthreads();
    }
}

// ---------------------------------------------------------------------------
// Launch
// ---------------------------------------------------------------------------
extern "C" void kernel_launch(void* const* d_in, const int* in_sizes, int n_in,
                              void* d_out, int out_size)
{
    const float* u    = (const float*)d_in[0];
    const float* iv   = (const float*)d_in[1];
    const float* a    = (const float*)d_in[2];
    const float* o    = (const float*)d_in[3];
    const void*  s    = d_in[4];
    const float* aoW0 = (const float*)d_in[5];
    const float* aob0 = (const float*)d_in[6];
    const float* aoW1 = (const float*)d_in[7];
    const float* aob1 = (const float*)d_in[8];
    const float* uiW0 = (const float*)d_in[9];
    const float* uib0 = (const float*)d_in[10];
    const float* uiW1 = (const float*)d_in[11];
    const float* uib1 = (const float*)d_in[12];
    float* out = (float*)d_out;

    cudaFuncSetAttribute(ao_kernel, cudaFuncAttributeMaxDynamicSharedMemorySize, SMEM_BYTES);
    int nsm = 148;
    cudaDeviceGetAttribute(&nsm, cudaDevAttrMultiProcessorCount, 0);

    ui_kernel<<<B_ / 8, 128>>>(u, iv, uiW0, uib0, uiW1, uib1, s);
    ao_kernel<<<nsm, TPB, SMEM_BYTES>>>(a, o, s, aoW0, aob0, aoW1, aob1, out, nsm);
}

// round 5
// speedup vs baseline: 2.1912x; 2.1865x over previous
#include <cuda_runtime.h>
#include <cuda_bf16.h>

#define B_    8192
#define NPAIR 32
#define BN    (B_ * NPAIR)
#define RREL  3
#define KP    136            // padded bf16 row stride (conflict-free)

__device__ float g_ui[B_ * 64];
__device__ int   g_cnt[RREL];
__device__ int   g_items[RREL * BN];

__device__ __forceinline__ float lrelu(float x) { return x >= 0.f ? x : 0.01f * x; }

__device__ __forceinline__ void split2(float x0, float x1, unsigned& hi, unsigned& lo) {
    __nv_bfloat16 h0 = __float2bfloat16(x0), h1 = __float2bfloat16(x1);
    float l0 = x0 - __bfloat162float(h0), l1 = x1 - __bfloat162float(h1);
    __nv_bfloat16 e0 = __float2bfloat16(l0), e1 = __float2bfloat16(l1);
    hi = ((unsigned)__bfloat16_as_ushort(h1) << 16) | (unsigned)__bfloat16_as_ushort(h0);
    lo = ((unsigned)__bfloat16_as_ushort(e1) << 16) | (unsigned)__bfloat16_as_ushort(e0);
}

#define MMA(d, a, b) \
    asm volatile("mma.sync.aligned.m16n8k16.row.col.f32.bf16.bf16.f32 " \
        "{%0,%1,%2,%3}, {%4,%5,%6,%7}, {%8,%9}, {%0,%1,%2,%3};" \
        : "+f"((d)[0]), "+f"((d)[1]), "+f"((d)[2]), "+f"((d)[3]) \
        : "r"((a)[0]), "r"((a)[1]), "r"((a)[2]), "r"((a)[3]), "r"((b)[0]), "r"((b)[1]))

// ---------------- kernel A: ui branch (unchanged, passing) ----------------
__global__ __launch_bounds__(128) void ui_kernel(
    const float* __restrict__ u, const float* __restrict__ iv,
    const float* __restrict__ W0, const float* __restrict__ b0,
    const float* __restrict__ W1, const float* __restrict__ b1)
{
    __shared__ float sx[8][128];
    __shared__ float sh[8][128];
    int tid = threadIdx.x;
    int row0 = blockIdx.x * 8;
    #pragma unroll
    for (int rr = 0; rr < 8; rr++) {
        int row = row0 + rr;
        sx[rr][tid] = (tid < 64) ? u[row * 64 + tid] : iv[row * 64 + tid - 64];
    }
    __syncthreads();
    float acc[8];
    #pragma unroll
    for (int rr = 0; rr < 8; rr++) acc[rr] = 0.f;
    #pragma unroll 4
    for (int k = 0; k < 128; k++) {
        float w = W0[k * 128 + tid];
        #pragma unroll
        for (int rr = 0; rr < 8; rr++) acc[rr] += sx[rr][k] * w;
    }
    float bb = b0[tid];
    #pragma unroll
    for (int rr = 0; rr < 8; rr++) sh[rr][tid] = lrelu(acc[rr] + bb);
    __syncthreads();
    int j = tid & 63, rb = (tid >> 6) * 4;
    float a2[4] = {0.f, 0.f, 0.f, 0.f};
    #pragma unroll 4
    for (int k = 0; k < 128; k++) {
        float w = W1[k * 64 + j];
        #pragma unroll
        for (int q = 0; q < 4; q++) a2[q] += sh[rb + q][k] * w;
    }
    float b2 = b1[j];
    #pragma unroll
    for (int q = 0; q < 4; q++) g_ui[(row0 + rb + q) * 64 + j] = lrelu(a2[q] + b2);
}

// ---------------- zero + bin kernels ----------------
__global__ void zero_cnt_kernel() {
    if (threadIdx.x < RREL) g_cnt[threadIdx.x] = 0;
}

__global__ __launch_bounds__(512) void bin_kernel(const void* __restrict__ s_raw)
{
    __shared__ int bc[RREL], bb[RREL], sis64;
    int tid = threadIdx.x;
    if (tid == 0) {
        const int* p = (const int*)s_raw;
        int any = 0;
        for (int q = 1; q < 257; q += 2) any |= p[q];
        sis64 = (any == 0);
        bc[0] = bc[1] = bc[2] = 0;
    }
    __syncthreads();
    int it = blockIdx.x * 512 + tid;
    const int* s32 = (const int*)s_raw;
    int sv = sis64 ? s32[2 * it] : s32[it];
    sv = min(max(sv, 0), RREL - 1);
    int pos = atomicAdd(&bc[sv], 1);
    __syncthreads();
    if (tid < RREL) bb[tid] = atomicAdd(&g_cnt[tid], bc[tid]);
    __syncthreads();
    g_items[sv * BN + bb[sv] + pos] = it;
}

// ---------------- kernel C: bf16 mma.sync AO branch ----------------
// smem byte offsets; all bf16 tiles row-major with KP=136 stride
#define XH_OFF    0                          // X hi / H hi: 128 x 136 bf16
#define XL_OFF    34816                      // X lo / H lo
#define W0H_OFF   69632                      // W0^T hi: [n=128][k=136]
#define W0L_OFF   104448
#define W1H_OFF   139264                     // W1^T hi: [o=64][h=136]
#define W1L_OFF   156672
#define SB0_OFF   174080                     // float[128]
#define SB1_OFF   174592                     // float[64]
#define SL_OFF    174848                     // int[128]
#define SRED_OFF  175360                     // float[128][4]
#define SMEM_TOT  177408

__global__ __launch_bounds__(512, 1) void ao_mma_kernel(
    const float* __restrict__ a_emb, const float* __restrict__ o_emb,
    const float* __restrict__ aoW0, const float* __restrict__ aob0,
    const float* __restrict__ aoW1, const float* __restrict__ aob1,
    float* __restrict__ out)
{
    extern __shared__ char smem[];
    float* sb0  = (float*)(smem + SB0_OFF);
    float* sb1  = (float*)(smem + SB1_OFF);
    int*   sl   = (int*)(smem + SL_OFF);
    float* sred = (float*)(smem + SRED_OFF);

    int tid = threadIdx.x, wid = tid >> 5, lane = tid & 31;
    int gq = lane >> 2, t = lane & 3;   // mma group / thread-in-group

    int cnt[RREL], nch[RREL];
    #pragma unroll
    for (int r = 0; r < RREL; r++) { cnt[r] = g_cnt[r]; nch[r] = (cnt[r] + 127) >> 7; }
    int tot = nch[0] + nch[1] + nch[2];
    int per = (tot + gridDim.x - 1) / gridDim.x;
    int c_lo = blockIdx.x * per, c_hi = min(tot, c_lo + per);
    int cur_r = -1;

    for (int c = c_lo; c < c_hi; c++) {
        int r, ci;
        if (c < nch[0])               { r = 0; ci = c; }
        else if (c < nch[0] + nch[1]) { r = 1; ci = c - nch[0]; }
        else                          { r = 2; ci = c - nch[0] - nch[1]; }
        int base = ci << 7;
        int valid = min(128, cnt[r] - base);

        // ---- weight staging on relation change (split into hi/lo bf16, transposed) ----
        if (r != cur_r) {
            cur_r = r;
            const float* w0g = aoW0 + (size_t)r * 16384;   // [k=128][n=128]
            for (int idx = tid; idx < 8192; idx += 512) {
                int n = idx & 127, k = (idx >> 7) * 2;
                unsigned hi, lo;
                split2(w0g[k * 128 + n], w0g[(k + 1) * 128 + n], hi, lo);
                *(unsigned*)(smem + W0H_OFF + (n * KP + k) * 2) = hi;
                *(unsigned*)(smem + W0L_OFF + (n * KP + k) * 2) = lo;
            }
            const float* w1g = aoW1 + (size_t)r * 8192;    // [h=128][o=64]
            for (int idx = tid; idx < 4096; idx += 512) {
                int o = idx & 63, h = (idx >> 6) * 2;
                unsigned hi, lo;
                split2(w1g[h * 64 + o], w1g[(h + 1) * 64 + o], hi, lo);
                *(unsigned*)(smem + W1H_OFF + (o * KP + h) * 2) = hi;
                *(unsigned*)(smem + W1L_OFF + (o * KP + h) * 2) = lo;
            }
            if (tid < 128) sb0[tid] = aob0[r * 128 + tid];
            if (tid < 64)  sb1[tid] = aob1[r * 64 + tid];
        }

        // ---- stage item list + gather X (split hi/lo) ----
        if (tid < 128) sl[tid] = (tid < valid) ? g_items[r * BN + base + tid] : -1;
        __syncthreads();
        {
            int row = tid >> 2, q = tid & 3;
            int g = sl[row];
            int cb = q * 32;
            const float* src = (q < 2) ? a_emb + (size_t)max(g, 0) * 64 + cb
                                       : o_emb + (size_t)max(g, 0) * 64 + (cb - 64);
            #pragma unroll
            for (int i = 0; i < 8; i++) {
                float4 v = (g >= 0) ? *(const float4*)(src + i * 4)
                                    : make_float4(0.f, 0.f, 0.f, 0.f);
                unsigned h0, l0, h1, l1;
                split2(v.x, v.y, h0, l0);
                split2(v.z, v.w, h1, l1);
                int cc = cb + i * 4;
                *(unsigned*)(smem + XH_OFF + (row * KP + cc) * 2)     = h0;
                *(unsigned*)(smem + XH_OFF + (row * KP + cc + 2) * 2) = h1;
                *(unsigned*)(smem + XL_OFF + (row * KP + cc) * 2)     = l0;
                *(unsigned*)(smem + XL_OFF + (row * KP + cc + 2) * 2) = l1;
            }
        }
        __syncthreads();

        // ---- GEMM1: D1[128,128] = X @ W0, 3-term bf16 split ----
        int mrow = (wid & 3) * 32, ncol = (wid >> 2) * 32;
        float acc[2][4][4];
        #pragma unroll
        for (int i = 0; i < 2; i++)
            #pragma unroll
            for (int j = 0; j < 4; j++)
                #pragma unroll
                for (int q = 0; q < 4; q++) acc[i][j][q] = 0.f;

        #pragma unroll
        for (int kt = 0; kt < 8; kt++) {
            int kb = kt * 16 + 2 * t;
            unsigned ah[2][4], al[2][4], bh[4][2], bl[4][2];
            #pragma unroll
            for (int ma = 0; ma < 2; ma++) {
                int rr0 = mrow + ma * 16 + gq;
                ah[ma][0] = *(unsigned*)(smem + XH_OFF + (rr0 * KP + kb) * 2);
                ah[ma][1] = *(unsigned*)(smem + XH_OFF + ((rr0 + 8) * KP + kb) * 2);
                ah[ma][2] = *(unsigned*)(smem + XH_OFF + (rr0 * KP + kb + 8) * 2);
                ah[ma][3] = *(unsigned*)(smem + XH_OFF + ((rr0 + 8) * KP + kb + 8) * 2);
                al[ma][0] = *(unsigned*)(smem + XL_OFF + (rr0 * KP + kb) * 2);
                al[ma][1] = *(unsigned*)(smem + XL_OFF + ((rr0 + 8) * KP + kb) * 2);
                al[ma][2] = *(unsigned*)(smem + XL_OFF + (rr0 * KP + kb + 8) * 2);
                al[ma][3] = *(unsigned*)(smem + XL_OFF + ((rr0 + 8) * KP + kb + 8) * 2);
            }
            #pragma unroll
            for (int na = 0; na < 4; na++) {
                int nn = ncol + na * 8 + gq;
                bh[na][0] = *(unsigned*)(smem + W0H_OFF + (nn * KP + kb) * 2);
                bh[na][1] = *(unsigned*)(smem + W0H_OFF + (nn * KP + kb + 8) * 2);
                bl[na][0] = *(unsigned*)(smem + W0L_OFF + (nn * KP + kb) * 2);
                bl[na][1] = *(unsigned*)(smem + W0L_OFF + (nn * KP + kb + 8) * 2);
            }
            #pragma unroll
            for (int ma = 0; ma < 2; ma++)
                #pragma unroll
                for (int na = 0; na < 4; na++) {
                    MMA(acc[ma][na], ah[ma], bh[na]);
                    MMA(acc[ma][na], ah[ma], bl[na]);
                    MMA(acc[ma][na], al[ma], bh[na]);
                }
        }
        __syncthreads();   // all X reads done before overwrite with H

        // ---- epilogue 1: H = lrelu(D1 + b0), split in place of X ----
        #pragma unroll
        for (int ma = 0; ma < 2; ma++) {
            int rr0 = mrow + ma * 16 + gq;
            #pragma unroll
            for (int na = 0; na < 4; na++) {
                int cc = ncol + na * 8 + 2 * t;
                float h0 = lrelu(acc[ma][na][0] + sb0[cc]);
                float h1 = lrelu(acc[ma][na][1] + sb0[cc + 1]);
                float h2 = lrelu(acc[ma][na][2] + sb0[cc]);
                float h3 = lrelu(acc[ma][na][3] + sb0[cc + 1]);
                unsigned hi, lo;
                split2(h0, h1, hi, lo);
                *(unsigned*)(smem + XH_OFF + (rr0 * KP + cc) * 2) = hi;
                *(unsigned*)(smem + XL_OFF + (rr0 * KP + cc) * 2) = lo;
                split2(h2, h3, hi, lo);
                *(unsigned*)(smem + XH_OFF + ((rr0 + 8) * KP + cc) * 2) = hi;
                *(unsigned*)(smem + XL_OFF + ((rr0 + 8) * KP + cc) * 2) = lo;
            }
        }
        __syncthreads();

        // ---- GEMM2: D2[128,64] = H @ W1 ----
        int mrow2 = (wid & 3) * 32, ncol2 = (wid >> 2) * 16;
        float acc2[2][2][4];
        #pragma unroll
        for (int i = 0; i < 2; i++)
            #pragma unroll
            for (int j = 0; j < 2; j++)
                #pragma unroll
                for (int q = 0; q < 4; q++) acc2[i][j][q] = 0.f;

        #pragma unroll
        for (int kt = 0; kt < 8; kt++) {
            int kb = kt * 16 + 2 * t;
            unsigned ah[2][4], al[2][4], bh[2][2], bl[2][2];
            #pragma unroll
            for (int ma = 0; ma < 2; ma++) {
                int rr0 = mrow2 + ma * 16 + gq;
                ah[ma][0] = *(unsigned*)(smem + XH_OFF + (rr0 * KP + kb) * 2);
                ah[ma][1] = *(unsigned*)(smem + XH_OFF + ((rr0 + 8) * KP + kb) * 2);
                ah[ma][2] = *(unsigned*)(smem + XH_OFF + (rr0 * KP + kb + 8) * 2);
                ah[ma][3] = *(unsigned*)(smem + XH_OFF + ((rr0 + 8) * KP + kb + 8) * 2);
                al[ma][0] = *(unsigned*)(smem + XL_OFF + (rr0 * KP + kb) * 2);
                al[ma][1] = *(unsigned*)(smem + XL_OFF + ((rr0 + 8) * KP + kb) * 2);
                al[ma][2] = *(unsigned*)(smem + XL_OFF + (rr0 * KP + kb + 8) * 2);
                al[ma][3] = *(unsigned*)(smem + XL_OFF + ((rr0 + 8) * KP + kb + 8) * 2);
            }
            #pragma unroll
            for (int na = 0; na < 2; na++) {
                int nn = ncol2 + na * 8 + gq;
                bh[na][0] = *(unsigned*)(smem + W1H_OFF + (nn * KP + kb) * 2);
                bh[na][1] = *(unsigned*)(smem + W1H_OFF + (nn * KP + kb + 8) * 2);
                bl[na][0] = *(unsigned*)(smem + W1L_OFF + (nn * KP + kb) * 2);
                bl[na][1] = *(unsigned*)(smem + W1L_OFF + (nn * KP + kb + 8) * 2);
            }
            #pragma unroll
            for (int ma = 0; ma < 2; ma++)
                #pragma unroll
                for (int na = 0; na < 2; na++) {
                    MMA(acc2[ma][na], ah[ma], bh[na]);
                    MMA(acc2[ma][na], ah[ma], bl[na]);
                    MMA(acc2[ma][na], al[ma], bh[na]);
                }
        }

        // ---- epilogue 2: o = lrelu(D2 + b1); partial dot with ui; reduce ----
        #pragma unroll
        for (int ma = 0; ma < 2; ma++) {
            #pragma unroll
            for (int half = 0; half < 2; half++) {
                int row = mrow2 + ma * 16 + gq + half * 8;
                int g = sl[row];
                const float* uiP = g_ui + (size_t)(max(g, 0) >> 5) * 64;
                float p = 0.f;
                #pragma unroll
                for (int na = 0; na < 2; na++) {
                    int cc = ncol2 + na * 8 + 2 * t;
                    float2 uv = *(const float2*)(uiP + cc);
                    float o0 = lrelu(acc2[ma][na][half * 2]     + sb1[cc]);
                    float o1 = lrelu(acc2[ma][na][half * 2 + 1] + sb1[cc + 1]);
                    p += o0 * uv.x + o1 * uv.y;
                }
                p += __shfl_xor_sync(0xffffffffu, p, 1);
                p += __shfl_xor_sync(0xffffffffu, p, 2);
                if (t == 0) sred[row * 4 + (wid >> 2)] = p;
            }
        }
        __syncthreads();
        if (tid < 128) {
            int g = sl[tid];
            if (g >= 0)
                out[g] = sred[tid * 4] + sred[tid * 4 + 1] + sred[tid * 4 + 2] + sred[tid * 4 + 3];
        }
        __syncthreads();
    }
}

// ---------------- launch ----------------
extern "C" void kernel_launch(void* const* d_in, const int* in_sizes, int n_in,
                              void* d_out, int out_size)
{
    const float* u    = (const float*)d_in[0];
    const float* iv   = (const float*)d_in[1];
    const float* a    = (const float*)d_in[2];
    const float* o    = (const float*)d_in[3];
    const void*  s    = d_in[4];
    const float* aoW0 = (const float*)d_in[5];
    const float* aob0 = (const float*)d_in[6];
    const float* aoW1 = (const float*)d_in[7];
    const float* aob1 = (const float*)d_in[8];
    const float* uiW0 = (const float*)d_in[9];
    const float* uib0 = (const float*)d_in[10];
    const float* uiW1 = (const float*)d_in[11];
    const float* uib1 = (const float*)d_in[12];
    float* out = (float*)d_out;

    cudaFuncSetAttribute(ao_mma_kernel, cudaFuncAttributeMaxDynamicSharedMemorySize, SMEM_TOT);
    int nsm = 148;
    cudaDeviceGetAttribute(&nsm, cudaDevAttrMultiProcessorCount, 0);

    zero_cnt_kernel<<<1, 32>>>();
    bin_kernel<<<BN / 512, 512>>>(s);
    ui_kernel<<<B_ / 8, 128>>>(u, iv, uiW0, uib0, uiW1, uib1);
    ao_mma_kernel<<<nsm, 512, SMEM_TOT>>>(a, o, aoW0, aob0, aoW1, aob1, out);
}